// round 13
// baseline (speedup 1.0000x reference)
#include <cuda_runtime.h>
#include <cuda_bf16.h>
#include <math_constants.h>
#include <cstdint>

#define BATCH 8
#define E 1024
#define HEADS 16
#define W 1024
#define DH 64

// ---------------------------------------------------------------------------
// Scratch (static __device__ arrays; no allocation anywhere)
// ---------------------------------------------------------------------------
__device__ __nv_bfloat16 g_ph[(size_t)3 * BATCH * E * W];  // K,Q,V projections hi
__device__ __nv_bfloat16 g_pl[(size_t)3 * BATCH * E * W];  // K,Q,V projections lo
__device__ float g_O[(size_t)BATCH * E * W];               // attention output (fp32)
__device__ __nv_bfloat16 g_wh[(size_t)4 * E * E];          // weights hi: LK,LQ,LV,DM
__device__ __nv_bfloat16 g_wl[(size_t)4 * E * E];          // weights lo

__device__ __forceinline__ uint32_t smem_u32(const void* p) {
    uint32_t a;
    asm("{ .reg .u64 t; cvta.to.shared.u64 t, %1; cvt.u32.u64 %0, t; }" : "=r"(a) : "l"(p));
    return a;
}
__device__ __forceinline__ void cp16(uint32_t dst, const void* src) {
    asm volatile("cp.async.cg.shared.global [%0], [%1], 16;"
                 :: "r"(dst), "l"(__cvta_generic_to_global(src)) : "memory");
}
#define CP_COMMIT() asm volatile("cp.async.commit_group;" ::: "memory")
#define CP_WAIT(n)  asm volatile("cp.async.wait_group %0;" :: "n"(n) : "memory")

__device__ __forceinline__ void ldsm_x4(uint32_t addr, uint32_t& r0, uint32_t& r1,
                                        uint32_t& r2, uint32_t& r3) {
    asm volatile("ldmatrix.sync.aligned.m8n8.x4.shared.b16 {%0,%1,%2,%3}, [%4];"
                 : "=r"(r0), "=r"(r1), "=r"(r2), "=r"(r3) : "r"(addr));
}
__device__ __forceinline__ void ldsm_x4_t(uint32_t addr, uint32_t& r0, uint32_t& r1,
                                          uint32_t& r2, uint32_t& r3) {
    asm volatile("ldmatrix.sync.aligned.m8n8.x4.trans.shared.b16 {%0,%1,%2,%3}, [%4];"
                 : "=r"(r0), "=r"(r1), "=r"(r2), "=r"(r3) : "r"(addr));
}
__device__ __forceinline__ void mma_bf16(float* c, const uint32_t* a, const uint32_t* b) {
    asm volatile("mma.sync.aligned.m16n8k16.row.col.f32.bf16.bf16.f32 "
                 "{%0,%1,%2,%3}, {%4,%5,%6,%7}, {%8,%9}, {%0,%1,%2,%3};"
                 : "+f"(c[0]), "+f"(c[1]), "+f"(c[2]), "+f"(c[3])
                 : "r"(a[0]), "r"(a[1]), "r"(a[2]), "r"(a[3]), "r"(b[0]), "r"(b[1]));
}
__device__ __forceinline__ void cvt_pack(float a, float b, uint32_t& hi, uint32_t& lo) {
    __nv_bfloat162 h = __floats2bfloat162_rn(a, b);
    float ra = a - __bfloat162float(h.x);
    float rb = b - __bfloat162float(h.y);
    __nv_bfloat162 l = __floats2bfloat162_rn(ra, rb);
    hi = *reinterpret_cast<uint32_t*>(&h);
    lo = *reinterpret_cast<uint32_t*>(&l);
}

// ---------------------------------------------------------------------------
// fp32 -> bf16 hi/lo splitter, all 4 weight matrices in one launch
// ---------------------------------------------------------------------------
struct Split4Args { const float* s0; const float* s1; const float* s2; const float* s3; };

__global__ __launch_bounds__(256) void split4_kernel(Split4Args a,
                                                     __nv_bfloat16* __restrict__ h,
                                                     __nv_bfloat16* __restrict__ l,
                                                     int n4each)
{
    const float* src = (blockIdx.y == 0) ? a.s0 : (blockIdx.y == 1) ? a.s1
                     : (blockIdx.y == 2) ? a.s2 : a.s3;
    const size_t eoff = (size_t)blockIdx.y * n4each;
    __nv_bfloat16* hh = h + eoff * 4;
    __nv_bfloat16* ll = l + eoff * 4;
    int i = blockIdx.x * blockDim.x + threadIdx.x;
    const int stride = gridDim.x * blockDim.x;
    for (; i < n4each; i += stride) {
        float4 v = reinterpret_cast<const float4*>(src)[i];
        uint32_t h01, l01, h23, l23;
        cvt_pack(v.x, v.y, h01, l01);
        cvt_pack(v.z, v.w, h23, l23);
        reinterpret_cast<uint2*>(hh)[i] = make_uint2(h01, h23);
        reinterpret_cast<uint2*>(ll)[i] = make_uint2(l01, l23);
    }
}

// ---------------------------------------------------------------------------
// HMMA bf16x3 GEMM — BK=64 (halved barrier count vs R12).
//   A: pre-split bf16 hi/lo via cp.async double buffer (2 stages).
//   B: fp32 activations, direct LDG -> cvt -> STS fill, SINGLE buffer.
// C[z] = A[z>>3] @ X[z] ; CTA 128x128, 8 warps (2x4), frag-cached MMA.
// Smem: AH[128x72bf16]=18432 | AL=18432  (x2 stages = 73728)
//       BH[64x272B]=17408 | BL=17408    (single, at 73728 / 91136)
// Total = 108544 B per CTA; 2 CTAs = 217 KB <= 228 KB carveout.
// ---------------------------------------------------------------------------
#define A_ST    36864
#define OFF_BH  73728
#define OFF_BL  91136
#define G_SMEM  108544

template <bool OUT_BF16>
__global__ __launch_bounds__(256, 2) void gemm_hyb(
    const __nv_bfloat16* __restrict__ Ah, const __nv_bfloat16* __restrict__ Al,
    int aStride,
    const float* __restrict__ X, float* __restrict__ Cf,
    __nv_bfloat16* __restrict__ Ch, __nv_bfloat16* __restrict__ Cl,
    const float* __restrict__ bias)
{
    extern __shared__ char smem[];
    const uint32_t sb = smem_u32(smem);
    const int t    = threadIdx.x;
    const int wid  = t >> 5;
    const int lane = t & 31;
    const int wm   = wid & 1;
    const int wn   = wid >> 1;
    const int z    = blockIdx.z;
    const int m0   = blockIdx.y * 128;
    const int n0   = blockIdx.x * 128;

    const __nv_bfloat16* Ahz = Ah + (size_t)(z >> 3) * aStride;
    const __nv_bfloat16* Alz = Al + (size_t)(z >> 3) * aStride;
    const float*         Xz  = X + (size_t)z * E * W;

    const int a_row = (lane & 7) + ((lane >> 3) & 1) * 8;
    const int a_k   = ((lane >> 4) & 1) * 8;
    const int b_k   = a_row;
    const int b_n   = a_k;

    // A chunk c (64 k) -> stage st: 128 rows x 64 bf16 hi + lo
    auto issueA = [&](int c, int st) {
        const int kc = c * 64;
        const uint32_t base = sb + st * A_ST;
#pragma unroll
        for (int i = 0; i < 4; i++) {
            int idx = i * 256 + t;           // 0..1023
            int row = idx >> 3;              // 0..127
            int kq  = idx & 7;               // 8 bf16 each
            size_t g = (size_t)(m0 + row) * E + kc + kq * 8;
            uint32_t d = base + row * 144 + kq * 16;
            cp16(d, Ahz + g);
            cp16(d + 18432, Alz + g);
        }
        CP_COMMIT();
    };

    float acc[4][4][4];
#pragma unroll
    for (int i = 0; i < 4; i++)
#pragma unroll
        for (int j = 0; j < 4; j++)
#pragma unroll
            for (int r = 0; r < 4; r++) acc[i][j][r] = 0.f;

    issueA(0, 0);

    for (int c = 0; c < 16; c++) {
        const int cur = c & 1;
        const int kc  = c * 64;
        // ---- fill B (single buffer): LDG fp32 -> cvt -> STS bf16 hi/lo ----
#pragma unroll
        for (int it = 0; it < 8; it++) {
            int idx = it * 256 + t;          // 0..2047
            int kr  = idx >> 5;              // 0..63
            int nq  = idx & 31;              // 4 floats each
            float4 v = *reinterpret_cast<const float4*>(
                &Xz[(size_t)(kc + kr) * W + n0 + nq * 4]);
            uint32_t h01, l01, h23, l23;
            cvt_pack(v.x, v.y, h01, l01);
            cvt_pack(v.z, v.w, h23, l23);
            char* p = reinterpret_cast<char*>(smem) + kr * 272 + nq * 8;
            *reinterpret_cast<uint2*>(p + OFF_BH) = make_uint2(h01, h23);
            *reinterpret_cast<uint2*>(p + OFF_BL) = make_uint2(l01, l23);
        }
        if (c < 15) { issueA(c + 1, cur ^ 1); CP_WAIT(1); }
        else        { CP_WAIT(0); }
        __syncthreads();

        const uint32_t base = sb + cur * A_ST;
#pragma unroll
        for (int s = 0; s < 4; s++) {
            uint32_t aH[4][4];
#pragma unroll
            for (int i = 0; i < 4; i++)
                ldsm_x4(base + (wm * 64 + i * 16 + a_row) * 144 + (s * 16 + a_k) * 2,
                        aH[i][0], aH[i][1], aH[i][2], aH[i][3]);
            uint32_t bH[4][2];
#pragma unroll
            for (int j = 0; j < 2; j++) {
                uint32_t r0, r1, r2, r3;
                ldsm_x4_t(sb + OFF_BH + (s * 16 + b_k) * 272 + (wn * 32 + j * 16 + b_n) * 2,
                          r0, r1, r2, r3);
                bH[j * 2 + 0][0] = r0; bH[j * 2 + 0][1] = r1;
                bH[j * 2 + 1][0] = r2; bH[j * 2 + 1][1] = r3;
            }
#pragma unroll
            for (int i = 0; i < 4; i++)
#pragma unroll
                for (int j = 0; j < 4; j++)
                    mma_bf16(acc[i][j], aH[i], bH[j]);          // hi*hi
            uint32_t bL[4][2];
#pragma unroll
            for (int j = 0; j < 2; j++) {
                uint32_t r0, r1, r2, r3;
                ldsm_x4_t(sb + OFF_BL + (s * 16 + b_k) * 272 + (wn * 32 + j * 16 + b_n) * 2,
                          r0, r1, r2, r3);
                bL[j * 2 + 0][0] = r0; bL[j * 2 + 0][1] = r1;
                bL[j * 2 + 1][0] = r2; bL[j * 2 + 1][1] = r3;
            }
#pragma unroll
            for (int i = 0; i < 4; i++)
#pragma unroll
                for (int j = 0; j < 4; j++)
                    mma_bf16(acc[i][j], aH[i], bL[j]);          // hi*lo
            uint32_t aL[4][4];
#pragma unroll
            for (int i = 0; i < 4; i++)
                ldsm_x4(base + 18432 + (wm * 64 + i * 16 + a_row) * 144 + (s * 16 + a_k) * 2,
                        aL[i][0], aL[i][1], aL[i][2], aL[i][3]);
#pragma unroll
            for (int i = 0; i < 4; i++)
#pragma unroll
                for (int j = 0; j < 4; j++)
                    mma_bf16(acc[i][j], aL[i], bH[j]);          // lo*hi
        }
        __syncthreads();
    }

    const int gid  = lane >> 2;
    const int tid4 = lane & 3;
    if (OUT_BF16) {
        __nv_bfloat16* Chz = Ch + (size_t)z * E * W;
        __nv_bfloat16* Clz = Cl + (size_t)z * E * W;
#pragma unroll
        for (int i = 0; i < 4; i++) {
            const int r0 = m0 + wm * 64 + i * 16 + gid;
            const int r1 = r0 + 8;
#pragma unroll
            for (int j = 0; j < 4; j++) {
                const int cc = n0 + wn * 32 + j * 8 + tid4 * 2;
                uint32_t h, l;
                cvt_pack(acc[i][j][0], acc[i][j][1], h, l);
                *reinterpret_cast<uint32_t*>(&Chz[(size_t)r0 * W + cc]) = h;
                *reinterpret_cast<uint32_t*>(&Clz[(size_t)r0 * W + cc]) = l;
                cvt_pack(acc[i][j][2], acc[i][j][3], h, l);
                *reinterpret_cast<uint32_t*>(&Chz[(size_t)r1 * W + cc]) = h;
                *reinterpret_cast<uint32_t*>(&Clz[(size_t)r1 * W + cc]) = l;
            }
        }
    } else {
        float* Cz = Cf + (size_t)z * E * W;
#pragma unroll
        for (int i = 0; i < 4; i++) {
            const int r0 = m0 + wm * 64 + i * 16 + gid;
            const int r1 = r0 + 8;
            const float bv0 = bias ? bias[r0] : 0.f;
            const float bv1 = bias ? bias[r1] : 0.f;
#pragma unroll
            for (int j = 0; j < 4; j++) {
                const int cc = n0 + wn * 32 + j * 8 + tid4 * 2;
                *reinterpret_cast<float2*>(&Cz[(size_t)r0 * W + cc]) =
                    make_float2(acc[i][j][0] + bv0, acc[i][j][1] + bv0);
                *reinterpret_cast<float2*>(&Cz[(size_t)r1 * W + cc]) =
                    make_float2(acc[i][j][2] + bv1, acc[i][j][3] + bv1);
            }
        }
    }
}

// ---------------------------------------------------------------------------
// Fused flash attention — R12 version (unchanged; current best).
// ---------------------------------------------------------------------------
#define KPAD 72
#define QPAD 136
#define F_KTH 0
#define F_KTL (F_KTH + 128 * KPAD * 2)
#define F_QSH (F_KTL + 128 * KPAD * 2)
#define F_QSL (F_QSH + 64 * QPAD * 2)
#define F_VSH (F_QSL + 64 * QPAD * 2)
#define F_VSL (F_VSH + 64 * QPAD * 2)
#define F_TOTAL (F_VSL + 64 * QPAD * 2)
#define OSM_STRIDE 132

__global__ __launch_bounds__(256, 2) void flash_kernel(
    const __nv_bfloat16* __restrict__ Kh, const __nv_bfloat16* __restrict__ Kl,
    const __nv_bfloat16* __restrict__ Qh, const __nv_bfloat16* __restrict__ Ql,
    const __nv_bfloat16* __restrict__ Vh, const __nv_bfloat16* __restrict__ Vl,
    float* __restrict__ gO)
{
    extern __shared__ char sm[];
    __nv_bfloat16* KtH = reinterpret_cast<__nv_bfloat16*>(sm + F_KTH);
    __nv_bfloat16* KtL = reinterpret_cast<__nv_bfloat16*>(sm + F_KTL);

    const uint32_t sKtH = smem_u32(sm) + F_KTH;
    const uint32_t sKtL = smem_u32(sm) + F_KTL;
    const uint32_t sQsH = smem_u32(sm) + F_QSH;
    const uint32_t sQsL = smem_u32(sm) + F_QSL;
    const uint32_t sVsH = smem_u32(sm) + F_VSH;
    const uint32_t sVsL = smem_u32(sm) + F_VSL;

    const int t    = threadIdx.x;
    const int wid  = t >> 5;
    const int lane = t & 31;
    const int gid  = lane >> 2;
    const int tid4 = lane & 3;

    const int kt = gridDim.x - 1 - blockIdx.x;
    const int k0 = kt * 128;
    const size_t bho = (size_t)blockIdx.y * DH * W;
    const __nv_bfloat16* Khb = Kh + bho;
    const __nv_bfloat16* Klb = Kl + bho;
    const __nv_bfloat16* Qhb = Qh + bho;
    const __nv_bfloat16* Qlb = Ql + bho;
    const __nv_bfloat16* Vhb = Vh + bho;
    const __nv_bfloat16* Vlb = Vl + bho;
    float* Ob = gO + bho;

    const int a_row = (lane & 7) + ((lane >> 3) & 1) * 8;
    const int a_k   = ((lane >> 4) & 1) * 8;
    const int b_k   = a_row;
    const int b_n   = a_k;
    const int v_row = (lane & 7) + ((lane >> 4) & 1) * 8;
    const int v_col = ((lane >> 3) & 1) * 8;

#pragma unroll
    for (int it = 0; it < 16; it++) {
        int idx = it * 256 + t;
        int d   = idx >> 6;
        int kp  = (idx & 63) * 2;
        uint32_t vh = *reinterpret_cast<const uint32_t*>(&Khb[(size_t)d * W + k0 + kp]);
        uint32_t vl = *reinterpret_cast<const uint32_t*>(&Klb[(size_t)d * W + k0 + kp]);
        __nv_bfloat162 h2 = *reinterpret_cast<__nv_bfloat162*>(&vh);
        __nv_bfloat162 l2 = *reinterpret_cast<__nv_bfloat162*>(&vl);
        KtH[(kp + 0) * KPAD + d] = h2.x;
        KtH[(kp + 1) * KPAD + d] = h2.y;
        KtL[(kp + 0) * KPAD + d] = l2.x;
        KtL[(kp + 1) * KPAD + d] = l2.y;
    }

    float m0 = -1e30f, m1 = -1e30f;
    float l0 = 0.f, l1 = 0.f;
    float oacc[8][4];
#pragma unroll
    for (int n = 0; n < 8; n++)
#pragma unroll
        for (int r = 0; r < 4; r++) oacc[n][r] = 0.f;

    for (int qt = 0; qt <= kt; qt++) {
        const int q0 = qt * 128;
        __syncthreads();

#pragma unroll
        for (int it = 0; it < 4; it++) {
            int idx = it * 256 + t;
            int d   = idx >> 4;
            int qc  = (idx & 15) * 8;
            size_t g = (size_t)d * W + q0 + qc;
            uint32_t o = d * (QPAD * 2) + qc * 2;
            cp16(sQsH + o, Qhb + g);
            cp16(sQsL + o, Qlb + g);
        }
        CP_COMMIT();
#pragma unroll
        for (int it = 0; it < 4; it++) {
            int idx = it * 256 + t;
            int d   = idx >> 4;
            int qc  = (idx & 15) * 8;
            size_t g = (size_t)d * W + q0 + qc;
            uint32_t o = d * (QPAD * 2) + qc * 2;
            cp16(sVsH + o, Vhb + g);
            cp16(sVsL + o, Vlb + g);
        }
        CP_COMMIT();
        CP_WAIT(1);
        __syncthreads();

#pragma unroll
        for (int half = 0; half < 2; half++) {
            const int qh = half * 64;
            const bool skip = (qt == kt) && (half == 1) && (wid < 4);

            float sacc[8][4];
#pragma unroll
            for (int j = 0; j < 8; j++)
#pragma unroll
                for (int r = 0; r < 4; r++) sacc[j][r] = 0.f;

            if (!skip) {
#pragma unroll
                for (int s = 0; s < 4; s++) {
                    uint32_t aH[4], aL[4];
                    ldsm_x4(sKtH + ((wid * 16 + a_row) * KPAD + s * 16 + a_k) * 2,
                            aH[0], aH[1], aH[2], aH[3]);
                    ldsm_x4(sKtL + ((wid * 16 + a_row) * KPAD + s * 16 + a_k) * 2,
                            aL[0], aL[1], aL[2], aL[3]);
#pragma unroll
                    for (int j = 0; j < 2; j++) {
                        uint32_t r0, r1, r2, r3, r4, r5, r6, r7;
                        ldsm_x4_t(sQsH + ((s * 16 + b_k) * QPAD + qh + j * 32 + b_n) * 2,
                                  r0, r1, r2, r3);
                        ldsm_x4_t(sQsH + ((s * 16 + b_k) * QPAD + qh + j * 32 + 16 + b_n) * 2,
                                  r4, r5, r6, r7);
                        uint32_t h0[2] = {r0, r1}, h1[2] = {r2, r3};
                        uint32_t h2[2] = {r4, r5}, h3[2] = {r6, r7};
                        mma_bf16(sacc[j * 4 + 0], aH, h0);
                        mma_bf16(sacc[j * 4 + 1], aH, h1);
                        mma_bf16(sacc[j * 4 + 2], aH, h2);
                        mma_bf16(sacc[j * 4 + 3], aH, h3);
                        mma_bf16(sacc[j * 4 + 0], aL, h0);
                        mma_bf16(sacc[j * 4 + 1], aL, h1);
                        mma_bf16(sacc[j * 4 + 2], aL, h2);
                        mma_bf16(sacc[j * 4 + 3], aL, h3);
                        uint32_t s0, s1, s2, s3, s4, s5, s6, s7;
                        ldsm_x4_t(sQsL + ((s * 16 + b_k) * QPAD + qh + j * 32 + b_n) * 2,
                                  s0, s1, s2, s3);
                        ldsm_x4_t(sQsL + ((s * 16 + b_k) * QPAD + qh + j * 32 + 16 + b_n) * 2,
                                  s4, s5, s6, s7);
                        uint32_t g0[2] = {s0, s1}, g1[2] = {s2, s3};
                        uint32_t g2[2] = {s4, s5}, g3[2] = {s6, s7};
                        mma_bf16(sacc[j * 4 + 0], aH, g0);
                        mma_bf16(sacc[j * 4 + 1], aH, g1);
                        mma_bf16(sacc[j * 4 + 2], aH, g2);
                        mma_bf16(sacc[j * 4 + 3], aH, g3);
                    }
                }
            }

            if (half == 0) {
                CP_WAIT(0);
                __syncthreads();
            }
            if (skip) continue;

            if (qt == kt) {
                const int r0 = wid * 16 + gid;
                const int r1 = r0 + 8;
#pragma unroll
                for (int j = 0; j < 8; j++) {
                    int qb = qh + j * 8 + tid4 * 2;
                    if (qb     > r0) sacc[j][0] = -1e30f;
                    if (qb + 1 > r0) sacc[j][1] = -1e30f;
                    if (qb     > r1) sacc[j][2] = -1e30f;
                    if (qb + 1 > r1) sacc[j][3] = -1e30f;
                }
            }

            float mx0 = -1e30f, mx1 = -1e30f;
#pragma unroll
            for (int j = 0; j < 8; j++) {
                mx0 = fmaxf(mx0, fmaxf(sacc[j][0], sacc[j][1]));
                mx1 = fmaxf(mx1, fmaxf(sacc[j][2], sacc[j][3]));
            }
            mx0 = fmaxf(mx0, __shfl_xor_sync(0xffffffff, mx0, 1));
            mx0 = fmaxf(mx0, __shfl_xor_sync(0xffffffff, mx0, 2));
            mx1 = fmaxf(mx1, __shfl_xor_sync(0xffffffff, mx1, 1));
            mx1 = fmaxf(mx1, __shfl_xor_sync(0xffffffff, mx1, 2));

            const float nm0 = fmaxf(m0, mx0);
            const float nm1 = fmaxf(m1, mx1);
            const float sc0 = __expf(m0 - nm0);
            const float sc1 = __expf(m1 - nm1);
            float sum0 = 0.f, sum1 = 0.f;
#pragma unroll
            for (int j = 0; j < 8; j++) {
                sacc[j][0] = __expf(sacc[j][0] - nm0);
                sacc[j][1] = __expf(sacc[j][1] - nm0);
                sacc[j][2] = __expf(sacc[j][2] - nm1);
                sacc[j][3] = __expf(sacc[j][3] - nm1);
                sum0 += sacc[j][0] + sacc[j][1];
                sum1 += sacc[j][2] + sacc[j][3];
            }
            sum0 += __shfl_xor_sync(0xffffffff, sum0, 1);
            sum0 += __shfl_xor_sync(0xffffffff, sum0, 2);
            sum1 += __shfl_xor_sync(0xffffffff, sum1, 1);
            sum1 += __shfl_xor_sync(0xffffffff, sum1, 2);
            l0 = l0 * sc0 + sum0;
            l1 = l1 * sc1 + sum1;
            m0 = nm0;
            m1 = nm1;
#pragma unroll
            for (int n = 0; n < 8; n++) {
                oacc[n][0] *= sc0;
                oacc[n][1] *= sc0;
                oacc[n][2] *= sc1;
                oacc[n][3] *= sc1;
            }

            uint32_t pH[16], pL[16];
#pragma unroll
            for (int s = 0; s < 4; s++) {
                cvt_pack(sacc[2 * s][0],     sacc[2 * s][1],     pH[s * 4 + 0], pL[s * 4 + 0]);
                cvt_pack(sacc[2 * s][2],     sacc[2 * s][3],     pH[s * 4 + 1], pL[s * 4 + 1]);
                cvt_pack(sacc[2 * s + 1][0], sacc[2 * s + 1][1], pH[s * 4 + 2], pL[s * 4 + 2]);
                cvt_pack(sacc[2 * s + 1][2], sacc[2 * s + 1][3], pH[s * 4 + 3], pL[s * 4 + 3]);
            }

#pragma unroll
            for (int s = 0; s < 4; s++) {
                const uint32_t colb = (qh + s * 16 + v_col) * 2;
#pragma unroll
                for (int j = 0; j < 2; j++) {
                    uint32_t r0, r1, r2, r3, r4, r5, r6, r7;
                    ldsm_x4(sVsH + (j * 32 + v_row) * (QPAD * 2) + colb, r0, r1, r2, r3);
                    ldsm_x4(sVsH + (j * 32 + 16 + v_row) * (QPAD * 2) + colb, r4, r5, r6, r7);
                    uint32_t h0[2] = {r0, r1}, h1[2] = {r2, r3};
                    uint32_t h2[2] = {r4, r5}, h3[2] = {r6, r7};
                    mma_bf16(oacc[j * 4 + 0], &pH[s * 4], h0);
                    mma_bf16(oacc[j * 4 + 1], &pH[s * 4], h1);
                    mma_bf16(oacc[j * 4 + 2], &pH[s * 4], h2);
                    mma_bf16(oacc[j * 4 + 3], &pH[s * 4], h3);
                    mma_bf16(oacc[j * 4 + 0], &pL[s * 4], h0);
                    mma_bf16(oacc[j * 4 + 1], &pL[s * 4], h1);
                    mma_bf16(oacc[j * 4 + 2], &pL[s * 4], h2);
                    mma_bf16(oacc[j * 4 + 3], &pL[s * 4], h3);
                    uint32_t s0, s1, s2, s3, s4, s5, s6, s7;
                    ldsm_x4(sVsL + (j * 32 + v_row) * (QPAD * 2) + colb, s0, s1, s2, s3);
                    ldsm_x4(sVsL + (j * 32 + 16 + v_row) * (QPAD * 2) + colb, s4, s5, s6, s7);
                    uint32_t g0[2] = {s0, s1}, g1[2] = {s2, s3};
                    uint32_t g2[2] = {s4, s5}, g3[2] = {s6, s7};
                    mma_bf16(oacc[j * 4 + 0], &pH[s * 4], g0);
                    mma_bf16(oacc[j * 4 + 1], &pH[s * 4], g1);
                    mma_bf16(oacc[j * 4 + 2], &pH[s * 4], g2);
                    mma_bf16(oacc[j * 4 + 3], &pH[s * 4], g3);
                }
            }
        }
    }

    const float inv0 = 0.03125f / l0;
    const float inv1 = 0.03125f / l1;
    __syncthreads();
    float* Osm = reinterpret_cast<float*>(sm);
    {
        const int r0 = wid * 16 + gid;
        const int r1 = r0 + 8;
#pragma unroll
        for (int n = 0; n < 8; n++) {
            int d0 = n * 8 + tid4 * 2;
            Osm[(d0 + 0) * OSM_STRIDE + r0] = oacc[n][0] * inv0;
            Osm[(d0 + 1) * OSM_STRIDE + r0] = oacc[n][1] * inv0;
            Osm[(d0 + 0) * OSM_STRIDE + r1] = oacc[n][2] * inv1;
            Osm[(d0 + 1) * OSM_STRIDE + r1] = oacc[n][3] * inv1;
        }
    }
    __syncthreads();
    {
        const int d  = t >> 2;
        const int kq = t & 3;
#pragma unroll
        for (int i = 0; i < 8; i++) {
            int k = (kq * 8 + i) * 4;
            float4 v = *reinterpret_cast<const float4*>(&Osm[d * OSM_STRIDE + k]);
            *reinterpret_cast<float4*>(&Ob[(size_t)d * W + k0 + k]) = v;
        }
    }
}

// ---------------------------------------------------------------------------
// Launch
// ---------------------------------------------------------------------------
extern "C" void kernel_launch(void* const* d_in, const int* in_sizes, int n_in,
                              void* d_out, int out_size)
{
    const float* x  = (const float*)d_in[0];   // slabs: 0=K-in, 1=Q-in, 2=V-in
    const float* LQ = (const float*)d_in[1];
    const float* LK = (const float*)d_in[2];
    const float* LV = (const float*)d_in[3];
    const float* DM = (const float*)d_in[4];
    const float* Db = (const float*)d_in[5];
    float* out = (float*)d_out;

    float* pO;
    __nv_bfloat16 *wh, *wl, *ph, *pl;
    cudaGetSymbolAddress((void**)&pO, g_O);
    cudaGetSymbolAddress((void**)&wh, g_wh);
    cudaGetSymbolAddress((void**)&wl, g_wl);
    cudaGetSymbolAddress((void**)&ph, g_ph);
    cudaGetSymbolAddress((void**)&pl, g_pl);

    cudaFuncSetAttribute(gemm_hyb<true>,  cudaFuncAttributeMaxDynamicSharedMemorySize, G_SMEM);
    cudaFuncSetAttribute(gemm_hyb<false>, cudaFuncAttributeMaxDynamicSharedMemorySize, G_SMEM);
    cudaFuncSetAttribute(flash_kernel,    cudaFuncAttributeMaxDynamicSharedMemorySize, F_TOTAL);

    const size_t BEW = (size_t)BATCH * E * W;
    const int EE4 = (int)((size_t)E * E / 4);

    Split4Args sa = {LK, LQ, LV, DM};
    split4_kernel<<<dim3(256, 4), 256>>>(sa, wh, wl, EE4);

    // projections: z = p*8 + b -> weight slab p, x slab p, bf16 hi/lo out slab p
    dim3 gProj(W / 128, E / 128, 3 * BATCH);
    gemm_hyb<true><<<gProj, 256, G_SMEM>>>(wh, wl, E * E, x, nullptr, ph, pl, nullptr);

    // flash attention: K slab 0, Q slab 1, V slab 2 (hi/lo)
    dim3 gFl(W / 128, BATCH * HEADS);
    flash_kernel<<<gFl, 256, F_TOTAL>>>(ph, pl, ph + BEW, pl + BEW,
                                        ph + 2 * BEW, pl + 2 * BEW, pO);

    // dense output projection (fp32 + bias)
    dim3 gD(W / 128, E / 128, BATCH);
    gemm_hyb<false><<<gD, 256, G_SMEM>>>(wh + 3 * (size_t)E * E, wl + 3 * (size_t)E * E, 0,
                                         pO, out, nullptr, nullptr, Db);
}

// round 15
// speedup vs baseline: 1.0618x; 1.0618x over previous
#include <cuda_runtime.h>
#include <cuda_bf16.h>
#include <math_constants.h>
#include <cstdint>

#define BATCH 8
#define E 1024
#define HEADS 16
#define W 1024
#define DH 64

// ---------------------------------------------------------------------------
// Scratch (static __device__ arrays; no allocation anywhere)
// ---------------------------------------------------------------------------
__device__ __nv_bfloat16 g_ph[(size_t)3 * BATCH * E * W];  // K,Q,V projections hi
__device__ __nv_bfloat16 g_pl[(size_t)3 * BATCH * E * W];  // K,Q,V projections lo
__device__ float g_O[(size_t)BATCH * E * W];               // attention output (fp32)
__device__ __nv_bfloat16 g_wh[(size_t)4 * E * E];          // weights hi: LK,LQ,LV,DM
__device__ __nv_bfloat16 g_wl[(size_t)4 * E * E];          // weights lo

__device__ __forceinline__ uint32_t smem_u32(const void* p) {
    uint32_t a;
    asm("{ .reg .u64 t; cvta.to.shared.u64 t, %1; cvt.u32.u64 %0, t; }" : "=r"(a) : "l"(p));
    return a;
}
__device__ __forceinline__ void cp16(uint32_t dst, const void* src) {
    asm volatile("cp.async.cg.shared.global [%0], [%1], 16;"
                 :: "r"(dst), "l"(__cvta_generic_to_global(src)) : "memory");
}
#define CP_COMMIT() asm volatile("cp.async.commit_group;" ::: "memory")
#define CP_WAIT(n)  asm volatile("cp.async.wait_group %0;" :: "n"(n) : "memory")

__device__ __forceinline__ void ldsm_x4(uint32_t addr, uint32_t& r0, uint32_t& r1,
                                        uint32_t& r2, uint32_t& r3) {
    asm volatile("ldmatrix.sync.aligned.m8n8.x4.shared.b16 {%0,%1,%2,%3}, [%4];"
                 : "=r"(r0), "=r"(r1), "=r"(r2), "=r"(r3) : "r"(addr));
}
__device__ __forceinline__ void ldsm_x4_t(uint32_t addr, uint32_t& r0, uint32_t& r1,
                                          uint32_t& r2, uint32_t& r3) {
    asm volatile("ldmatrix.sync.aligned.m8n8.x4.trans.shared.b16 {%0,%1,%2,%3}, [%4];"
                 : "=r"(r0), "=r"(r1), "=r"(r2), "=r"(r3) : "r"(addr));
}
__device__ __forceinline__ void mma_bf16(float* c, const uint32_t* a, const uint32_t* b) {
    asm volatile("mma.sync.aligned.m16n8k16.row.col.f32.bf16.bf16.f32 "
                 "{%0,%1,%2,%3}, {%4,%5,%6,%7}, {%8,%9}, {%0,%1,%2,%3};"
                 : "+f"(c[0]), "+f"(c[1]), "+f"(c[2]), "+f"(c[3])
                 : "r"(a[0]), "r"(a[1]), "r"(a[2]), "r"(a[3]), "r"(b[0]), "r"(b[1]));
}
__device__ __forceinline__ void cvt_pack(float a, float b, uint32_t& hi, uint32_t& lo) {
    __nv_bfloat162 h = __floats2bfloat162_rn(a, b);
    float ra = a - __bfloat162float(h.x);
    float rb = b - __bfloat162float(h.y);
    __nv_bfloat162 l = __floats2bfloat162_rn(ra, rb);
    hi = *reinterpret_cast<uint32_t*>(&h);
    lo = *reinterpret_cast<uint32_t*>(&l);
}

// ---------------------------------------------------------------------------
// fp32 -> bf16 hi/lo splitter, all 4 weight matrices in one launch
// ---------------------------------------------------------------------------
struct Split4Args { const float* s0; const float* s1; const float* s2; const float* s3; };

__global__ __launch_bounds__(256) void split4_kernel(Split4Args a,
                                                     __nv_bfloat16* __restrict__ h,
                                                     __nv_bfloat16* __restrict__ l,
                                                     int n4each)
{
    const float* src = (blockIdx.y == 0) ? a.s0 : (blockIdx.y == 1) ? a.s1
                     : (blockIdx.y == 2) ? a.s2 : a.s3;
    const size_t eoff = (size_t)blockIdx.y * n4each;
    __nv_bfloat16* hh = h + eoff * 4;
    __nv_bfloat16* ll = l + eoff * 4;
    int i = blockIdx.x * blockDim.x + threadIdx.x;
    const int stride = gridDim.x * blockDim.x;
    for (; i < n4each; i += stride) {
        float4 v = reinterpret_cast<const float4*>(src)[i];
        uint32_t h01, l01, h23, l23;
        cvt_pack(v.x, v.y, h01, l01);
        cvt_pack(v.z, v.w, h23, l23);
        reinterpret_cast<uint2*>(hh)[i] = make_uint2(h01, h23);
        reinterpret_cast<uint2*>(ll)[i] = make_uint2(l01, l23);
    }
}

// ---------------------------------------------------------------------------
// HMMA bf16x3 GEMM — R12 schedule (fastest measured, BK=32).
//   A: pre-split bf16 hi/lo via cp.async double buffer.
//   B: fp32 activations, direct LDG -> cvt -> STS fill.
// Stage: AH 10240 | AL 10240 | BH 8704 | BL 8704 = 37888
// ---------------------------------------------------------------------------
#define OFF_AH 0
#define OFF_AL 10240
#define OFF_BH 20480
#define OFF_BL 29184
#define ST_BYTES 37888
#define G_SMEM  (2 * ST_BYTES)

template <bool OUT_BF16>
__global__ __launch_bounds__(256, 2) void gemm_hyb(
    const __nv_bfloat16* __restrict__ Ah, const __nv_bfloat16* __restrict__ Al,
    int aStride,
    const float* __restrict__ X, float* __restrict__ Cf,
    __nv_bfloat16* __restrict__ Ch, __nv_bfloat16* __restrict__ Cl,
    const float* __restrict__ bias)
{
    extern __shared__ char smem[];
    const uint32_t sb = smem_u32(smem);
    const int t    = threadIdx.x;
    const int wid  = t >> 5;
    const int lane = t & 31;
    const int wm   = wid & 1;
    const int wn   = wid >> 1;
    const int z    = blockIdx.z;
    const int m0   = blockIdx.y * 128;
    const int n0   = blockIdx.x * 128;

    const __nv_bfloat16* Ahz = Ah + (size_t)(z >> 3) * aStride;
    const __nv_bfloat16* Alz = Al + (size_t)(z >> 3) * aStride;
    const float*         Xz  = X + (size_t)z * E * W;

    const int a_row = (lane & 7) + ((lane >> 3) & 1) * 8;
    const int a_k   = ((lane >> 4) & 1) * 8;
    const int b_k   = a_row;
    const int b_n   = a_k;

    auto issueA = [&](int c, int st) {
        const int kc = c * 32;
        const uint32_t base = sb + st * ST_BYTES;
#pragma unroll
        for (int i = 0; i < 2; i++) {
            int idx = i * 256 + t;
            int row = idx >> 2;
            int kq  = idx & 3;
            size_t g = (size_t)(m0 + row) * E + kc + kq * 8;
            uint32_t d = base + OFF_AH + row * 80 + kq * 16;
            cp16(d, Ahz + g);
            cp16(d + (OFF_AL - OFF_AH), Alz + g);
        }
        CP_COMMIT();
    };

    float acc[4][4][4];
#pragma unroll
    for (int i = 0; i < 4; i++)
#pragma unroll
        for (int j = 0; j < 4; j++)
#pragma unroll
            for (int r = 0; r < 4; r++) acc[i][j][r] = 0.f;

    issueA(0, 0);

    for (int c = 0; c < 32; c++) {
        const int cur = c & 1;
        const int kc  = c * 32;
        // ---- fill B stage: direct LDG fp32 -> cvt -> STS bf16 hi/lo ----
#pragma unroll
        for (int it = 0; it < 4; it++) {
            int idx = it * 256 + t;
            int kr  = idx >> 5;
            int nq  = idx & 31;
            float4 v = *reinterpret_cast<const float4*>(
                &Xz[(size_t)(kc + kr) * W + n0 + nq * 4]);
            uint32_t h01, l01, h23, l23;
            cvt_pack(v.x, v.y, h01, l01);
            cvt_pack(v.z, v.w, h23, l23);
            char* p = reinterpret_cast<char*>(smem) + cur * ST_BYTES + kr * 272 + nq * 8;
            *reinterpret_cast<uint2*>(p + OFF_BH) = make_uint2(h01, h23);
            *reinterpret_cast<uint2*>(p + OFF_BL) = make_uint2(l01, l23);
        }
        if (c < 31) { issueA(c + 1, cur ^ 1); CP_WAIT(1); }
        else        { CP_WAIT(0); }
        __syncthreads();

        const uint32_t base = sb + cur * ST_BYTES;
#pragma unroll
        for (int s = 0; s < 2; s++) {
            uint32_t aH[4][4];
#pragma unroll
            for (int i = 0; i < 4; i++)
                ldsm_x4(base + OFF_AH + (wm * 64 + i * 16 + a_row) * 80 + (s * 16 + a_k) * 2,
                        aH[i][0], aH[i][1], aH[i][2], aH[i][3]);
            uint32_t bH[4][2];
#pragma unroll
            for (int j = 0; j < 2; j++) {
                uint32_t r0, r1, r2, r3;
                ldsm_x4_t(base + OFF_BH + (s * 16 + b_k) * 272 + (wn * 32 + j * 16 + b_n) * 2,
                          r0, r1, r2, r3);
                bH[j * 2 + 0][0] = r0; bH[j * 2 + 0][1] = r1;
                bH[j * 2 + 1][0] = r2; bH[j * 2 + 1][1] = r3;
            }
#pragma unroll
            for (int i = 0; i < 4; i++)
#pragma unroll
                for (int j = 0; j < 4; j++)
                    mma_bf16(acc[i][j], aH[i], bH[j]);          // hi*hi
            uint32_t bL[4][2];
#pragma unroll
            for (int j = 0; j < 2; j++) {
                uint32_t r0, r1, r2, r3;
                ldsm_x4_t(base + OFF_BL + (s * 16 + b_k) * 272 + (wn * 32 + j * 16 + b_n) * 2,
                          r0, r1, r2, r3);
                bL[j * 2 + 0][0] = r0; bL[j * 2 + 0][1] = r1;
                bL[j * 2 + 1][0] = r2; bL[j * 2 + 1][1] = r3;
            }
#pragma unroll
            for (int i = 0; i < 4; i++)
#pragma unroll
                for (int j = 0; j < 4; j++)
                    mma_bf16(acc[i][j], aH[i], bL[j]);          // hi*lo
            uint32_t aL[4][4];
#pragma unroll
            for (int i = 0; i < 4; i++)
                ldsm_x4(base + OFF_AL + (wm * 64 + i * 16 + a_row) * 80 + (s * 16 + a_k) * 2,
                        aL[i][0], aL[i][1], aL[i][2], aL[i][3]);
#pragma unroll
            for (int i = 0; i < 4; i++)
#pragma unroll
                for (int j = 0; j < 4; j++)
                    mma_bf16(acc[i][j], aL[i], bH[j]);          // lo*hi
        }
        __syncthreads();
    }

    const int gid  = lane >> 2;
    const int tid4 = lane & 3;
    if (OUT_BF16) {
        __nv_bfloat16* Chz = Ch + (size_t)z * E * W;
        __nv_bfloat16* Clz = Cl + (size_t)z * E * W;
#pragma unroll
        for (int i = 0; i < 4; i++) {
            const int r0 = m0 + wm * 64 + i * 16 + gid;
            const int r1 = r0 + 8;
#pragma unroll
            for (int j = 0; j < 4; j++) {
                const int cc = n0 + wn * 32 + j * 8 + tid4 * 2;
                uint32_t h, l;
                cvt_pack(acc[i][j][0], acc[i][j][1], h, l);
                *reinterpret_cast<uint32_t*>(&Chz[(size_t)r0 * W + cc]) = h;
                *reinterpret_cast<uint32_t*>(&Clz[(size_t)r0 * W + cc]) = l;
                cvt_pack(acc[i][j][2], acc[i][j][3], h, l);
                *reinterpret_cast<uint32_t*>(&Chz[(size_t)r1 * W + cc]) = h;
                *reinterpret_cast<uint32_t*>(&Clz[(size_t)r1 * W + cc]) = l;
            }
        }
    } else {
        float* Cz = Cf + (size_t)z * E * W;
#pragma unroll
        for (int i = 0; i < 4; i++) {
            const int r0 = m0 + wm * 64 + i * 16 + gid;
            const int r1 = r0 + 8;
            const float bv0 = bias ? bias[r0] : 0.f;
            const float bv1 = bias ? bias[r1] : 0.f;
#pragma unroll
            for (int j = 0; j < 4; j++) {
                const int cc = n0 + wn * 32 + j * 8 + tid4 * 2;
                *reinterpret_cast<float2*>(&Cz[(size_t)r0 * W + cc]) =
                    make_float2(acc[i][j][0] + bv0, acc[i][j][1] + bv0);
                *reinterpret_cast<float2*>(&Cz[(size_t)r1 * W + cc]) =
                    make_float2(acc[i][j][2] + bv1, acc[i][j][3] + bv1);
            }
        }
    }
}

// ---------------------------------------------------------------------------
// Fused flash attention — R12 body; R14: grid swapped so CTA submission is
// globally heavy-first (x = bh fastest, y = reversed kt).
// ---------------------------------------------------------------------------
#define KPAD 72
#define QPAD 136
#define F_KTH 0
#define F_KTL (F_KTH + 128 * KPAD * 2)
#define F_QSH (F_KTL + 128 * KPAD * 2)
#define F_QSL (F_QSH + 64 * QPAD * 2)
#define F_VSH (F_QSL + 64 * QPAD * 2)
#define F_VSL (F_VSH + 64 * QPAD * 2)
#define F_TOTAL (F_VSL + 64 * QPAD * 2)
#define OSM_STRIDE 132

__global__ __launch_bounds__(256, 2) void flash_kernel(
    const __nv_bfloat16* __restrict__ Kh, const __nv_bfloat16* __restrict__ Kl,
    const __nv_bfloat16* __restrict__ Qh, const __nv_bfloat16* __restrict__ Ql,
    const __nv_bfloat16* __restrict__ Vh, const __nv_bfloat16* __restrict__ Vl,
    float* __restrict__ gO)
{
    extern __shared__ char sm[];
    __nv_bfloat16* KtH = reinterpret_cast<__nv_bfloat16*>(sm + F_KTH);
    __nv_bfloat16* KtL = reinterpret_cast<__nv_bfloat16*>(sm + F_KTL);

    const uint32_t sKtH = smem_u32(sm) + F_KTH;
    const uint32_t sKtL = smem_u32(sm) + F_KTL;
    const uint32_t sQsH = smem_u32(sm) + F_QSH;
    const uint32_t sQsL = smem_u32(sm) + F_QSL;
    const uint32_t sVsH = smem_u32(sm) + F_VSH;
    const uint32_t sVsL = smem_u32(sm) + F_VSL;

    const int t    = threadIdx.x;
    const int wid  = t >> 5;
    const int lane = t & 31;
    const int gid  = lane >> 2;
    const int tid4 = lane & 3;

    // heavy-first: y = reversed kt (kt=7 CTAs submitted first, all bh)
    const int kt = gridDim.y - 1 - blockIdx.y;
    const int k0 = kt * 128;
    const size_t bho = (size_t)blockIdx.x * DH * W;
    const __nv_bfloat16* Khb = Kh + bho;
    const __nv_bfloat16* Klb = Kl + bho;
    const __nv_bfloat16* Qhb = Qh + bho;
    const __nv_bfloat16* Qlb = Ql + bho;
    const __nv_bfloat16* Vhb = Vh + bho;
    const __nv_bfloat16* Vlb = Vl + bho;
    float* Ob = gO + bho;

    const int a_row = (lane & 7) + ((lane >> 3) & 1) * 8;
    const int a_k   = ((lane >> 4) & 1) * 8;
    const int b_k   = a_row;
    const int b_n   = a_k;
    const int v_row = (lane & 7) + ((lane >> 4) & 1) * 8;
    const int v_col = ((lane >> 3) & 1) * 8;

#pragma unroll
    for (int it = 0; it < 16; it++) {
        int idx = it * 256 + t;
        int d   = idx >> 6;
        int kp  = (idx & 63) * 2;
        uint32_t vh = *reinterpret_cast<const uint32_t*>(&Khb[(size_t)d * W + k0 + kp]);
        uint32_t vl = *reinterpret_cast<const uint32_t*>(&Klb[(size_t)d * W + k0 + kp]);
        __nv_bfloat162 h2 = *reinterpret_cast<__nv_bfloat162*>(&vh);
        __nv_bfloat162 l2 = *reinterpret_cast<__nv_bfloat162*>(&vl);
        KtH[(kp + 0) * KPAD + d] = h2.x;
        KtH[(kp + 1) * KPAD + d] = h2.y;
        KtL[(kp + 0) * KPAD + d] = l2.x;
        KtL[(kp + 1) * KPAD + d] = l2.y;
    }

    float m0 = -1e30f, m1 = -1e30f;
    float l0 = 0.f, l1 = 0.f;
    float oacc[8][4];
#pragma unroll
    for (int n = 0; n < 8; n++)
#pragma unroll
        for (int r = 0; r < 4; r++) oacc[n][r] = 0.f;

    for (int qt = 0; qt <= kt; qt++) {
        const int q0 = qt * 128;
        __syncthreads();

#pragma unroll
        for (int it = 0; it < 4; it++) {
            int idx = it * 256 + t;
            int d   = idx >> 4;
            int qc  = (idx & 15) * 8;
            size_t g = (size_t)d * W + q0 + qc;
            uint32_t o = d * (QPAD * 2) + qc * 2;
            cp16(sQsH + o, Qhb + g);
            cp16(sQsL + o, Qlb + g);
        }
        CP_COMMIT();
#pragma unroll
        for (int it = 0; it < 4; it++) {
            int idx = it * 256 + t;
            int d   = idx >> 4;
            int qc  = (idx & 15) * 8;
            size_t g = (size_t)d * W + q0 + qc;
            uint32_t o = d * (QPAD * 2) + qc * 2;
            cp16(sVsH + o, Vhb + g);
            cp16(sVsL + o, Vlb + g);
        }
        CP_COMMIT();
        CP_WAIT(1);
        __syncthreads();

#pragma unroll
        for (int half = 0; half < 2; half++) {
            const int qh = half * 64;
            const bool skip = (qt == kt) && (half == 1) && (wid < 4);

            float sacc[8][4];
#pragma unroll
            for (int j = 0; j < 8; j++)
#pragma unroll
                for (int r = 0; r < 4; r++) sacc[j][r] = 0.f;

            if (!skip) {
#pragma unroll
                for (int s = 0; s < 4; s++) {
                    uint32_t aH[4], aL[4];
                    ldsm_x4(sKtH + ((wid * 16 + a_row) * KPAD + s * 16 + a_k) * 2,
                            aH[0], aH[1], aH[2], aH[3]);
                    ldsm_x4(sKtL + ((wid * 16 + a_row) * KPAD + s * 16 + a_k) * 2,
                            aL[0], aL[1], aL[2], aL[3]);
#pragma unroll
                    for (int j = 0; j < 2; j++) {
                        uint32_t r0, r1, r2, r3, r4, r5, r6, r7;
                        ldsm_x4_t(sQsH + ((s * 16 + b_k) * QPAD + qh + j * 32 + b_n) * 2,
                                  r0, r1, r2, r3);
                        ldsm_x4_t(sQsH + ((s * 16 + b_k) * QPAD + qh + j * 32 + 16 + b_n) * 2,
                                  r4, r5, r6, r7);
                        uint32_t h0[2] = {r0, r1}, h1[2] = {r2, r3};
                        uint32_t h2[2] = {r4, r5}, h3[2] = {r6, r7};
                        mma_bf16(sacc[j * 4 + 0], aH, h0);
                        mma_bf16(sacc[j * 4 + 1], aH, h1);
                        mma_bf16(sacc[j * 4 + 2], aH, h2);
                        mma_bf16(sacc[j * 4 + 3], aH, h3);
                        mma_bf16(sacc[j * 4 + 0], aL, h0);
                        mma_bf16(sacc[j * 4 + 1], aL, h1);
                        mma_bf16(sacc[j * 4 + 2], aL, h2);
                        mma_bf16(sacc[j * 4 + 3], aL, h3);
                        uint32_t s0, s1, s2, s3, s4, s5, s6, s7;
                        ldsm_x4_t(sQsL + ((s * 16 + b_k) * QPAD + qh + j * 32 + b_n) * 2,
                                  s0, s1, s2, s3);
                        ldsm_x4_t(sQsL + ((s * 16 + b_k) * QPAD + qh + j * 32 + 16 + b_n) * 2,
                                  s4, s5, s6, s7);
                        uint32_t g0[2] = {s0, s1}, g1[2] = {s2, s3};
                        uint32_t g2[2] = {s4, s5}, g3[2] = {s6, s7};
                        mma_bf16(sacc[j * 4 + 0], aH, g0);
                        mma_bf16(sacc[j * 4 + 1], aH, g1);
                        mma_bf16(sacc[j * 4 + 2], aH, g2);
                        mma_bf16(sacc[j * 4 + 3], aH, g3);
                    }
                }
            }

            if (half == 0) {
                CP_WAIT(0);
                __syncthreads();
            }
            if (skip) continue;

            if (qt == kt) {
                const int r0 = wid * 16 + gid;
                const int r1 = r0 + 8;
#pragma unroll
                for (int j = 0; j < 8; j++) {
                    int qb = qh + j * 8 + tid4 * 2;
                    if (qb     > r0) sacc[j][0] = -1e30f;
                    if (qb + 1 > r0) sacc[j][1] = -1e30f;
                    if (qb     > r1) sacc[j][2] = -1e30f;
                    if (qb + 1 > r1) sacc[j][3] = -1e30f;
                }
            }

            float mx0 = -1e30f, mx1 = -1e30f;
#pragma unroll
            for (int j = 0; j < 8; j++) {
                mx0 = fmaxf(mx0, fmaxf(sacc[j][0], sacc[j][1]));
                mx1 = fmaxf(mx1, fmaxf(sacc[j][2], sacc[j][3]));
            }
            mx0 = fmaxf(mx0, __shfl_xor_sync(0xffffffff, mx0, 1));
            mx0 = fmaxf(mx0, __shfl_xor_sync(0xffffffff, mx0, 2));
            mx1 = fmaxf(mx1, __shfl_xor_sync(0xffffffff, mx1, 1));
            mx1 = fmaxf(mx1, __shfl_xor_sync(0xffffffff, mx1, 2));

            const float nm0 = fmaxf(m0, mx0);
            const float nm1 = fmaxf(m1, mx1);
            const float sc0 = __expf(m0 - nm0);
            const float sc1 = __expf(m1 - nm1);
            float sum0 = 0.f, sum1 = 0.f;
#pragma unroll
            for (int j = 0; j < 8; j++) {
                sacc[j][0] = __expf(sacc[j][0] - nm0);
                sacc[j][1] = __expf(sacc[j][1] - nm0);
                sacc[j][2] = __expf(sacc[j][2] - nm1);
                sacc[j][3] = __expf(sacc[j][3] - nm1);
                sum0 += sacc[j][0] + sacc[j][1];
                sum1 += sacc[j][2] + sacc[j][3];
            }
            sum0 += __shfl_xor_sync(0xffffffff, sum0, 1);
            sum0 += __shfl_xor_sync(0xffffffff, sum0, 2);
            sum1 += __shfl_xor_sync(0xffffffff, sum1, 1);
            sum1 += __shfl_xor_sync(0xffffffff, sum1, 2);
            l0 = l0 * sc0 + sum0;
            l1 = l1 * sc1 + sum1;
            m0 = nm0;
            m1 = nm1;
#pragma unroll
            for (int n = 0; n < 8; n++) {
                oacc[n][0] *= sc0;
                oacc[n][1] *= sc0;
                oacc[n][2] *= sc1;
                oacc[n][3] *= sc1;
            }

            uint32_t pH[16], pL[16];
#pragma unroll
            for (int s = 0; s < 4; s++) {
                cvt_pack(sacc[2 * s][0],     sacc[2 * s][1],     pH[s * 4 + 0], pL[s * 4 + 0]);
                cvt_pack(sacc[2 * s][2],     sacc[2 * s][3],     pH[s * 4 + 1], pL[s * 4 + 1]);
                cvt_pack(sacc[2 * s + 1][0], sacc[2 * s + 1][1], pH[s * 4 + 2], pL[s * 4 + 2]);
                cvt_pack(sacc[2 * s + 1][2], sacc[2 * s + 1][3], pH[s * 4 + 3], pL[s * 4 + 3]);
            }

#pragma unroll
            for (int s = 0; s < 4; s++) {
                const uint32_t colb = (qh + s * 16 + v_col) * 2;
#pragma unroll
                for (int j = 0; j < 2; j++) {
                    uint32_t r0, r1, r2, r3, r4, r5, r6, r7;
                    ldsm_x4(sVsH + (j * 32 + v_row) * (QPAD * 2) + colb, r0, r1, r2, r3);
                    ldsm_x4(sVsH + (j * 32 + 16 + v_row) * (QPAD * 2) + colb, r4, r5, r6, r7);
                    uint32_t h0[2] = {r0, r1}, h1[2] = {r2, r3};
                    uint32_t h2[2] = {r4, r5}, h3[2] = {r6, r7};
                    mma_bf16(oacc[j * 4 + 0], &pH[s * 4], h0);
                    mma_bf16(oacc[j * 4 + 1], &pH[s * 4], h1);
                    mma_bf16(oacc[j * 4 + 2], &pH[s * 4], h2);
                    mma_bf16(oacc[j * 4 + 3], &pH[s * 4], h3);
                    mma_bf16(oacc[j * 4 + 0], &pL[s * 4], h0);
                    mma_bf16(oacc[j * 4 + 1], &pL[s * 4], h1);
                    mma_bf16(oacc[j * 4 + 2], &pL[s * 4], h2);
                    mma_bf16(oacc[j * 4 + 3], &pL[s * 4], h3);
                    uint32_t s0, s1, s2, s3, s4, s5, s6, s7;
                    ldsm_x4(sVsL + (j * 32 + v_row) * (QPAD * 2) + colb, s0, s1, s2, s3);
                    ldsm_x4(sVsL + (j * 32 + 16 + v_row) * (QPAD * 2) + colb, s4, s5, s6, s7);
                    uint32_t g0[2] = {s0, s1}, g1[2] = {s2, s3};
                    uint32_t g2[2] = {s4, s5}, g3[2] = {s6, s7};
                    mma_bf16(oacc[j * 4 + 0], &pH[s * 4], g0);
                    mma_bf16(oacc[j * 4 + 1], &pH[s * 4], g1);
                    mma_bf16(oacc[j * 4 + 2], &pH[s * 4], g2);
                    mma_bf16(oacc[j * 4 + 3], &pH[s * 4], g3);
                }
            }
        }
    }

    const float inv0 = 0.03125f / l0;
    const float inv1 = 0.03125f / l1;
    __syncthreads();
    float* Osm = reinterpret_cast<float*>(sm);
    {
        const int r0 = wid * 16 + gid;
        const int r1 = r0 + 8;
#pragma unroll
        for (int n = 0; n < 8; n++) {
            int d0 = n * 8 + tid4 * 2;
            Osm[(d0 + 0) * OSM_STRIDE + r0] = oacc[n][0] * inv0;
            Osm[(d0 + 1) * OSM_STRIDE + r0] = oacc[n][1] * inv0;
            Osm[(d0 + 0) * OSM_STRIDE + r1] = oacc[n][2] * inv1;
            Osm[(d0 + 1) * OSM_STRIDE + r1] = oacc[n][3] * inv1;
        }
    }
    __syncthreads();
    {
        const int d  = t >> 2;
        const int kq = t & 3;
#pragma unroll
        for (int i = 0; i < 8; i++) {
            int k = (kq * 8 + i) * 4;
            float4 v = *reinterpret_cast<const float4*>(&Osm[d * OSM_STRIDE + k]);
            *reinterpret_cast<float4*>(&Ob[(size_t)d * W + k0 + k]) = v;
        }
    }
}

// ---------------------------------------------------------------------------
// Launch
// ---------------------------------------------------------------------------
extern "C" void kernel_launch(void* const* d_in, const int* in_sizes, int n_in,
                              void* d_out, int out_size)
{
    const float* x  = (const float*)d_in[0];   // slabs: 0=K-in, 1=Q-in, 2=V-in
    const float* LQ = (const float*)d_in[1];
    const float* LK = (const float*)d_in[2];
    const float* LV = (const float*)d_in[3];
    const float* DM = (const float*)d_in[4];
    const float* Db = (const float*)d_in[5];
    float* out = (float*)d_out;

    float* pO;
    __nv_bfloat16 *wh, *wl, *ph, *pl;
    cudaGetSymbolAddress((void**)&pO, g_O);
    cudaGetSymbolAddress((void**)&wh, g_wh);
    cudaGetSymbolAddress((void**)&wl, g_wl);
    cudaGetSymbolAddress((void**)&ph, g_ph);
    cudaGetSymbolAddress((void**)&pl, g_pl);

    cudaFuncSetAttribute(gemm_hyb<true>,  cudaFuncAttributeMaxDynamicSharedMemorySize, G_SMEM);
    cudaFuncSetAttribute(gemm_hyb<false>, cudaFuncAttributeMaxDynamicSharedMemorySize, G_SMEM);
    cudaFuncSetAttribute(flash_kernel,    cudaFuncAttributeMaxDynamicSharedMemorySize, F_TOTAL);

    const size_t BEW = (size_t)BATCH * E * W;
    const int EE4 = (int)((size_t)E * E / 4);

    Split4Args sa = {LK, LQ, LV, DM};
    split4_kernel<<<dim3(256, 4), 256>>>(sa, wh, wl, EE4);

    // projections: z = p*8 + b -> weight slab p, x slab p, bf16 hi/lo out slab p
    dim3 gProj(W / 128, E / 128, 3 * BATCH);
    gemm_hyb<true><<<gProj, 256, G_SMEM>>>(wh, wl, E * E, x, nullptr, ph, pl, nullptr);

    // flash attention — heavy-first submission: x = bh, y = reversed kt
    dim3 gFl(BATCH * HEADS, W / 128);
    flash_kernel<<<gFl, 256, F_TOTAL>>>(ph, pl, ph + BEW, pl + BEW,
                                        ph + 2 * BEW, pl + 2 * BEW, pO);

    // dense output projection (fp32 + bias)
    dim3 gD(W / 128, E / 128, BATCH);
    gemm_hyb<false><<<gD, 256, G_SMEM>>>(wh + 3 * (size_t)E * E, wl + 3 * (size_t)E * E, 0,
                                         pO, out, nullptr, nullptr, Db);
}